// round 15
// baseline (speedup 1.0000x reference)
#include <cuda_runtime.h>
#include <cuda_fp16.h>

#define N_VUL 100000
#define N_SRC 50000
#define N_EDGE 500000
#define D 128
#define NREL 3
#define CAP 64            // max in-degree per (rel,dst). Poisson(5): P(>32)~1e-18.

#define FILL_BLOCKS 977
#define CONV_BLOCKS 2048

// Static scratch (allocation is forbidden).
__device__ int g_cur[NREL][N_VUL];              // per-(rel,dst) cursor == in-degree
__device__ int g_bucket[NREL][N_VUL][CAP];      // src ids per (rel,dst)  (76.8 MB)
__device__ __half g_xh[NREL][N_SRC][D];         // fp16 mirror of x tables (38.4 MB)

__global__ void zero_cursors() {
    const int tid    = blockIdx.x * blockDim.x + threadIdx.x;
    const int stride = gridDim.x * blockDim.x;
    int* cur = &g_cur[0][0];
    for (int i = tid; i < NREL * N_VUL; i += stride) cur[i] = 0;
}

// Fused kernel: blocks [0, FILL_BLOCKS) bucketize edges (atomic-latency-bound);
// blocks [FILL_BLOCKS, ...) convert x tables to fp16 (bandwidth-bound).
__global__ void fill_convert_kernel(const int* __restrict__ sa, const int* __restrict__ da,
                                    const int* __restrict__ sb, const int* __restrict__ db,
                                    const int* __restrict__ sc, const int* __restrict__ dc,
                                    const float4* __restrict__ xa,
                                    const float4* __restrict__ xb,
                                    const float4* __restrict__ xc) {
    if (blockIdx.x < FILL_BLOCKS) {
        const int tid    = blockIdx.x * blockDim.x + threadIdx.x;
        const int stride = FILL_BLOCKS * blockDim.x;
        for (int e = tid; e < N_EDGE; e += stride) {
            int d, p;
            d = da[e]; p = atomicAdd(&g_cur[0][d], 1); if (p < CAP) g_bucket[0][d][p] = sa[e];
            d = db[e]; p = atomicAdd(&g_cur[1][d], 1); if (p < CAP) g_bucket[1][d][p] = sb[e];
            d = dc[e]; p = atomicAdd(&g_cur[2][d], 1); if (p < CAP) g_bucket[2][d][p] = sc[e];
        }
    } else {
        const int tid    = (blockIdx.x - FILL_BLOCKS) * blockDim.x + threadIdx.x;
        const int stride = CONV_BLOCKS * blockDim.x;
        const int n4 = N_SRC * D / 4;                 // 1.6M float4 per table
        const float4* __restrict__ xs[NREL] = { xa, xb, xc };
#pragma unroll
        for (int r = 0; r < NREL; r++) {
            const float4* __restrict__ x = xs[r];
            uint2* __restrict__ dst = (uint2*)&g_xh[r][0][0];
            for (int i = tid; i < n4; i += stride) {
                const float4 v = x[i];
                __half2 h0 = __floats2half2_rn(v.x, v.y);
                __half2 h1 = __floats2half2_rn(v.z, v.w);
                uint2 packed;
                packed.x = *(const unsigned int*)&h0;
                packed.y = *(const unsigned int*)&h1;
                dst[i] = packed;
            }
        }
    }
}

// Sum up to n (<=32) gathered fp16 rows. Load pattern identical to the proven
// R10/R11 loop (shfl broadcast + 8B loads); arithmetic tail shrunk: groups of
// 4 edges accumulate in fp16 (HADD2) and flush to fp32 once per group.
// Remainder edges (n % 4) accumulate in exact fp32 as before.
__device__ __forceinline__ float4 batch_sum(const uint2* __restrict__ xh,
                                            int myidx, int n, int lane, float4 a) {
    int e = 0;
    const int n4 = n & ~3;
    for (; e < n4; e += 4) {
        __half2 h0 = __floats2half2_rn(0.f, 0.f);
        __half2 h1 = __floats2half2_rn(0.f, 0.f);
#pragma unroll
        for (int j = 0; j < 4; j++) {
            const int s = __shfl_sync(0xFFFFFFFFu, myidx, e + j);
            const uint2 hv = xh[s * (D / 4) + lane];  // 4 halves: cols 4*lane..+3
            h0 = __hadd2(h0, *(const __half2*)&hv.x);
            h1 = __hadd2(h1, *(const __half2*)&hv.y);
        }
        const float2 f0 = __half22float2(h0);
        const float2 f1 = __half22float2(h1);
        a.x += f0.x; a.y += f0.y; a.z += f1.x; a.w += f1.y;
    }
#pragma unroll 3
    for (; e < n; e++) {
        const int s = __shfl_sync(0xFFFFFFFFu, myidx, e);
        const uint2 hv = xh[s * (D / 4) + lane];
        const float2 f0 = __half22float2(*(const __half2*)&hv.x);
        const float2 f1 = __half22float2(*(const __half2*)&hv.y);
        a.x += f0.x; a.y += f0.y; a.z += f1.x; a.w += f1.y;
    }
    return a;
}

// One warp per destination row. Lane l owns float cols [4l, 4l+4).
// Structure identical to the proven R11 kernel (hoisted metadata, 3 relation
// blocks, plain loads/stores — cache hints reverted as neutral).
__global__ void pull_kernel(float4* __restrict__ out) {
    const int gtid = blockIdx.x * blockDim.x + threadIdx.x;
    const int dst  = gtid >> 5;
    const int lane = gtid & 31;
    if (dst >= N_VUL) return;

    // 3 independent count loads.
    const int cf0 = g_cur[0][dst];
    const int cf1 = g_cur[1][dst];
    const int cf2 = g_cur[2][dst];
    const int c0 = cf0 < CAP ? cf0 : CAP;
    const int c1 = cf1 < CAP ? cf1 : CAP;
    const int c2 = cf2 < CAP ? cf2 : CAP;

    const int* __restrict__ b0 = g_bucket[0][dst];
    const int* __restrict__ b1 = g_bucket[1][dst];
    const int* __restrict__ b2 = g_bucket[2][dst];

    // 3 independent first-batch entry loads.
    const int my0 = (lane < c0) ? b0[lane] : 0;
    const int my1 = (lane < c1) ? b1[lane] : 0;
    const int my2 = (lane < c2) ? b2[lane] : 0;

    const uint2* __restrict__ xh0 = (const uint2*)&g_xh[0][0][0];
    const uint2* __restrict__ xh1 = (const uint2*)&g_xh[1][0][0];
    const uint2* __restrict__ xh2 = (const uint2*)&g_xh[2][0][0];

    float4 acc = make_float4(0.f, 0.f, 0.f, 0.f);

    // relation 0
    {
        float4 a = make_float4(0.f, 0.f, 0.f, 0.f);
        a = batch_sum(xh0, my0, c0 < 32 ? c0 : 32, lane, a);
        for (int base = 32; base < c0; base += 32) {          // cold path
            int mi = (base + lane < c0) ? b0[base + lane] : 0;
            a = batch_sum(xh0, mi, (c0 - base) < 32 ? (c0 - base) : 32, lane, a);
        }
        const float recip = 1.0f / (3.0f * (float)(cf0 > 0 ? cf0 : 1));
        acc.x += a.x * recip; acc.y += a.y * recip;
        acc.z += a.z * recip; acc.w += a.w * recip;
    }
    // relation 1
    {
        float4 a = make_float4(0.f, 0.f, 0.f, 0.f);
        a = batch_sum(xh1, my1, c1 < 32 ? c1 : 32, lane, a);
        for (int base = 32; base < c1; base += 32) {          // cold path
            int mi = (base + lane < c1) ? b1[base + lane] : 0;
            a = batch_sum(xh1, mi, (c1 - base) < 32 ? (c1 - base) : 32, lane, a);
        }
        const float recip = 1.0f / (3.0f * (float)(cf1 > 0 ? cf1 : 1));
        acc.x += a.x * recip; acc.y += a.y * recip;
        acc.z += a.z * recip; acc.w += a.w * recip;
    }
    // relation 2
    {
        float4 a = make_float4(0.f, 0.f, 0.f, 0.f);
        a = batch_sum(xh2, my2, c2 < 32 ? c2 : 32, lane, a);
        for (int base = 32; base < c2; base += 32) {          // cold path
            int mi = (base + lane < c2) ? b2[base + lane] : 0;
            a = batch_sum(xh2, mi, (c2 - base) < 32 ? (c2 - base) : 32, lane, a);
        }
        const float recip = 1.0f / (3.0f * (float)(cf2 > 0 ? cf2 : 1));
        acc.x += a.x * recip; acc.y += a.y * recip;
        acc.z += a.z * recip; acc.w += a.w * recip;
    }

    out[dst * (D / 4) + lane] = acc;
}

extern "C" void kernel_launch(void* const* d_in, const int* in_sizes, int n_in,
                              void* d_out, int out_size) {
    // metadata order: x_a, x_b, x_c, src_a, dst_a, src_b, dst_b, src_c, dst_c
    const float* xa = (const float*)d_in[0];
    const float* xb = (const float*)d_in[1];
    const float* xc = (const float*)d_in[2];
    const int* sa = (const int*)d_in[3];
    const int* da = (const int*)d_in[4];
    const int* sb = (const int*)d_in[5];
    const int* db = (const int*)d_in[6];
    const int* sc = (const int*)d_in[7];
    const int* dc = (const int*)d_in[8];
    float* out = (float*)d_out;

    zero_cursors<<<296, 256>>>();
    fill_convert_kernel<<<FILL_BLOCKS + CONV_BLOCKS, 256>>>(
        sa, da, sb, db, sc, dc,
        (const float4*)xa, (const float4*)xb, (const float4*)xc);

    // 100000 dsts * 32 threads = 3.2M threads; 8 warps/block -> 12500 blocks
    pull_kernel<<<12500, 256>>>((float4*)out);
}

// round 16
// speedup vs baseline: 1.2264x; 1.2264x over previous
#include <cuda_runtime.h>
#include <cuda_fp16.h>

#define N_VUL 100000
#define N_SRC 50000
#define N_EDGE 500000
#define D 128
#define NREL 3
#define CAP 64            // max in-degree per (rel,dst). Poisson(5): P(>32)~1e-18.

#define FILL_BLOCKS 977
#define CONV_BLOCKS 2048

// Static scratch (allocation is forbidden).
__device__ int g_cur[NREL][N_VUL];              // per-(rel,dst) cursor == in-degree
__device__ int g_bucket[NREL][N_VUL][CAP];      // src ids per (rel,dst)  (76.8 MB)
__device__ __half g_xh[NREL][N_SRC][D];         // fp16 mirror of x tables (38.4 MB)

// Fused kernel: blocks [0, FILL_BLOCKS) bucketize edges (atomic-latency-bound);
// blocks [FILL_BLOCKS, ...) convert x tables to fp16 (bandwidth-bound).
__global__ void fill_convert_kernel(const int* __restrict__ sa, const int* __restrict__ da,
                                    const int* __restrict__ sb, const int* __restrict__ db,
                                    const int* __restrict__ sc, const int* __restrict__ dc,
                                    const float4* __restrict__ xa,
                                    const float4* __restrict__ xb,
                                    const float4* __restrict__ xc) {
    if (blockIdx.x < FILL_BLOCKS) {
        const int tid    = blockIdx.x * blockDim.x + threadIdx.x;
        const int stride = FILL_BLOCKS * blockDim.x;
        for (int e = tid; e < N_EDGE; e += stride) {
            int d, p;
            d = da[e]; p = atomicAdd(&g_cur[0][d], 1); if (p < CAP) g_bucket[0][d][p] = sa[e];
            d = db[e]; p = atomicAdd(&g_cur[1][d], 1); if (p < CAP) g_bucket[1][d][p] = sb[e];
            d = dc[e]; p = atomicAdd(&g_cur[2][d], 1); if (p < CAP) g_bucket[2][d][p] = sc[e];
        }
    } else {
        const int tid    = (blockIdx.x - FILL_BLOCKS) * blockDim.x + threadIdx.x;
        const int stride = CONV_BLOCKS * blockDim.x;
        const int n4 = N_SRC * D / 4;                 // 1.6M float4 per table
        const float4* __restrict__ xs[NREL] = { xa, xb, xc };
#pragma unroll
        for (int r = 0; r < NREL; r++) {
            const float4* __restrict__ x = xs[r];
            uint2* __restrict__ dst = (uint2*)&g_xh[r][0][0];
            for (int i = tid; i < n4; i += stride) {
                const float4 v = x[i];
                __half2 h0 = __floats2half2_rn(v.x, v.y);
                __half2 h1 = __floats2half2_rn(v.z, v.w);
                uint2 packed;
                packed.x = *(const unsigned int*)&h0;
                packed.y = *(const unsigned int*)&h1;
                dst[i] = packed;
            }
        }
    }
}

// Sum up to n (<=32) gathered fp16 rows (fp32 accumulate). Proven R10/R11
// inner loop: shfl broadcast + unroll 4, 8B loads. FROZEN — eight experiments
// (wider loads, predication, grouping, fp16 accum, cache hints, self-clean)
// all regressed. Do not restructure.
__device__ __forceinline__ float4 batch_sum(const uint2* __restrict__ xh,
                                            int myidx, int n, int lane, float4 a) {
#pragma unroll 4
    for (int e = 0; e < n; e++) {
        const int s = __shfl_sync(0xFFFFFFFFu, myidx, e);
        const uint2 h = xh[s * (D / 4) + lane];       // 4 halves: cols 4*lane..+3
        const float2 f0 = __half22float2(*(const __half2*)&h.x);
        const float2 f1 = __half22float2(*(const __half2*)&h.y);
        a.x += f0.x; a.y += f0.y; a.z += f1.x; a.w += f1.y;
    }
    return a;
}

// One warp per destination row. Lane l owns float cols [4l, 4l+4).
// Byte-identical to the proven 62.4us R10/R11 kernel (hoisted metadata).
__global__ void pull_kernel(float4* __restrict__ out) {
    const int gtid = blockIdx.x * blockDim.x + threadIdx.x;
    const int dst  = gtid >> 5;
    const int lane = gtid & 31;
    if (dst >= N_VUL) return;

    // 3 independent count loads.
    const int cf0 = g_cur[0][dst];
    const int cf1 = g_cur[1][dst];
    const int cf2 = g_cur[2][dst];
    const int c0 = cf0 < CAP ? cf0 : CAP;
    const int c1 = cf1 < CAP ? cf1 : CAP;
    const int c2 = cf2 < CAP ? cf2 : CAP;

    const int* __restrict__ b0 = g_bucket[0][dst];
    const int* __restrict__ b1 = g_bucket[1][dst];
    const int* __restrict__ b2 = g_bucket[2][dst];

    // 3 independent first-batch entry loads.
    const int my0 = (lane < c0) ? b0[lane] : 0;
    const int my1 = (lane < c1) ? b1[lane] : 0;
    const int my2 = (lane < c2) ? b2[lane] : 0;

    const uint2* __restrict__ xh0 = (const uint2*)&g_xh[0][0][0];
    const uint2* __restrict__ xh1 = (const uint2*)&g_xh[1][0][0];
    const uint2* __restrict__ xh2 = (const uint2*)&g_xh[2][0][0];

    float4 acc = make_float4(0.f, 0.f, 0.f, 0.f);

    // relation 0
    {
        float4 a = make_float4(0.f, 0.f, 0.f, 0.f);
        a = batch_sum(xh0, my0, c0 < 32 ? c0 : 32, lane, a);
        for (int base = 32; base < c0; base += 32) {          // cold path
            int mi = (base + lane < c0) ? b0[base + lane] : 0;
            a = batch_sum(xh0, mi, (c0 - base) < 32 ? (c0 - base) : 32, lane, a);
        }
        const float recip = 1.0f / (3.0f * (float)(cf0 > 0 ? cf0 : 1));
        acc.x += a.x * recip; acc.y += a.y * recip;
        acc.z += a.z * recip; acc.w += a.w * recip;
    }
    // relation 1
    {
        float4 a = make_float4(0.f, 0.f, 0.f, 0.f);
        a = batch_sum(xh1, my1, c1 < 32 ? c1 : 32, lane, a);
        for (int base = 32; base < c1; base += 32) {          // cold path
            int mi = (base + lane < c1) ? b1[base + lane] : 0;
            a = batch_sum(xh1, mi, (c1 - base) < 32 ? (c1 - base) : 32, lane, a);
        }
        const float recip = 1.0f / (3.0f * (float)(cf1 > 0 ? cf1 : 1));
        acc.x += a.x * recip; acc.y += a.y * recip;
        acc.z += a.z * recip; acc.w += a.w * recip;
    }
    // relation 2
    {
        float4 a = make_float4(0.f, 0.f, 0.f, 0.f);
        a = batch_sum(xh2, my2, c2 < 32 ? c2 : 32, lane, a);
        for (int base = 32; base < c2; base += 32) {          // cold path
            int mi = (base + lane < c2) ? b2[base + lane] : 0;
            a = batch_sum(xh2, mi, (c2 - base) < 32 ? (c2 - base) : 32, lane, a);
        }
        const float recip = 1.0f / (3.0f * (float)(cf2 > 0 ? cf2 : 1));
        acc.x += a.x * recip; acc.y += a.y * recip;
        acc.z += a.z * recip; acc.w += a.w * recip;
    }

    out[dst * (D / 4) + lane] = acc;
}

extern "C" void kernel_launch(void* const* d_in, const int* in_sizes, int n_in,
                              void* d_out, int out_size) {
    // metadata order: x_a, x_b, x_c, src_a, dst_a, src_b, dst_b, src_c, dst_c
    const float* xa = (const float*)d_in[0];
    const float* xb = (const float*)d_in[1];
    const float* xc = (const float*)d_in[2];
    const int* sa = (const int*)d_in[3];
    const int* da = (const int*)d_in[4];
    const int* sb = (const int*)d_in[5];
    const int* db = (const int*)d_in[6];
    const int* sc = (const int*)d_in[7];
    const int* dc = (const int*)d_in[8];
    float* out = (float*)d_out;

    // Zero the cursors via a graph-capturable memset node (replaces the
    // zero_cursors kernel launch; ~1.2 MB, not an allocation).
    void* cur_ptr = nullptr;
    cudaGetSymbolAddress(&cur_ptr, g_cur);
    cudaMemsetAsync(cur_ptr, 0, sizeof(int) * NREL * N_VUL, 0);

    fill_convert_kernel<<<FILL_BLOCKS + CONV_BLOCKS, 256>>>(
        sa, da, sb, db, sc, dc,
        (const float4*)xa, (const float4*)xb, (const float4*)xc);

    // 100000 dsts * 32 threads = 3.2M threads; 8 warps/block -> 12500 blocks
    pull_kernel<<<12500, 256>>>((float4*)out);
}